// round 16
// baseline (speedup 1.0000x reference)
#include <cuda_runtime.h>
#include <math.h>
#include <stdint.h>
#define B_ 4
#define V_ 20000
#define D_ 512
#define DH_ 64
#define L_ 4
#define DFF_ 2048
#define P_ 128
#define CW_ 192
#define STEPS_ 64
#define TK_ 50
#define NB 148
#define NT 512
#define NWARP (NB*16)
#define DD (D_*D_)
#define DXF (D_*DFF_)

__device__ float g_K[L_*B_*CW_*D_], g_Vv[L_*B_*CW_*D_];
__device__ float g_WqT[L_*DD], g_WkT[L_*DD], g_WvT[L_*DD], g_WoT[L_*DD];
__device__ float g_W1T[L_*DXF], g_W2T[L_*DXF];
__device__ float g_q[B_*P_*D_], g_xb[B_*P_*D_], g_yb[B_*P_*D_], g_ao[B_*P_*D_];
__device__ float g_hp[B_*P_*DFF_];
__device__ float g_y1[B_*D_], g_x1[L_*B_*D_], g_y2[L_*B_*D_];
__device__ float g_mask[B_*V_], g_dis[B_*V_];
__device__ int g_tok[B_*CW_], g_nv[B_];
__device__ unsigned g_arr = 0, g_rel = 0;

// epoch barrier: red.release arrival (fire&forget), block0 releases epoch
__device__ __forceinline__ void gsync(unsigned &ep){
    __syncthreads();
    ep += 1u;
    if (threadIdx.x == 0){
        asm volatile("red.release.gpu.add.u32 [%0], 1;" :: "l"(&g_arr) : "memory");
        if (blockIdx.x == 0){
            unsigned target = ep * (unsigned)NB, c;
            do { asm volatile("ld.acquire.gpu.u32 %0, [%1];" : "=r"(c) : "l"(&g_arr) : "memory"); } while (c < target);
            asm volatile("st.release.gpu.u32 [%0], %1;" :: "l"(&g_rel), "r"(ep) : "memory");
        } else {
            unsigned r;
            do { asm volatile("ld.acquire.gpu.u32 %0, [%1];" : "=r"(r) : "l"(&g_rel) : "memory"); } while (r < ep);
        }
    }
    __syncthreads();
}
__device__ __forceinline__ float gelu_f(float x){
    double xd = x;
    return (float)(0.5*xd*(1.0 + tanh(0.7978845608028654*(xd + 0.044715*xd*xd*xd))));
}
__device__ __forceinline__ float exp_acc(float x){ return (float)exp((double)x); }
__device__ __forceinline__ float blkSum(float v, volatile float* sh){
    int ln = threadIdx.x&31, w = threadIdx.x>>5;
    #pragma unroll
    for (int o=16;o;o>>=1) v += __shfl_down_sync(0xffffffffu,v,o);
    if (ln==0) sh[w]=v;
    __syncthreads();
    if (threadIdx.x==0){ float r=sh[0]; for(int i=1;i<16;i++) r+=sh[i]; sh[0]=r; }
    __syncthreads(); float r=sh[0]; __syncthreads(); return r;
}
__device__ __forceinline__ float blkMax(float v, volatile float* sh){
    int ln = threadIdx.x&31, w = threadIdx.x>>5;
    #pragma unroll
    for (int o=16;o;o>>=1) v = fmaxf(v,__shfl_down_sync(0xffffffffu,v,o));
    if (ln==0) sh[w]=v;
    __syncthreads();
    if (threadIdx.x==0){ float r=sh[0]; for(int i=1;i<16;i++) r=fmaxf(r,sh[i]); sh[0]=r; }
    __syncthreads(); float r=sh[0]; __syncthreads(); return r;
}
__device__ __forceinline__ float lnval(float v, volatile float* sh){
    float m = blkSum(v,sh)*(1.0f/D_);
    float d = v-m;
    float var = blkSum(d*d,sh)*(1.0f/D_);
    return d*(float)(1.0/sqrt((double)var+1e-6));
}
__device__ __forceinline__ unsigned ordf(float x){
    unsigned u=__float_as_uint(x);
    return u ^ (((unsigned)((int)u>>31)) | 0x80000000u);
}
__device__ __forceinline__ float dordf(unsigned e){
    unsigned u = (e&0x80000000u) ? (e^0x80000000u) : ~e;
    return __uint_as_float(u);
}
__device__ __forceinline__ uint32_t rot(uint32_t x,int r){ return (x<<r)|(x>>(32-r)); }
__device__ __forceinline__ void tf2x32(uint32_t k0,uint32_t k1,uint32_t&x0,uint32_t&x1){
    uint32_t k2 = k0^k1^0x1BD11BDAu;
    x0+=k0; x1+=k1;
    x0+=x1;x1=rot(x1,13);x1^=x0; x0+=x1;x1=rot(x1,15);x1^=x0; x0+=x1;x1=rot(x1,26);x1^=x0; x0+=x1;x1=rot(x1,6);x1^=x0;
    x0+=k1; x1+=k2+1u;
    x0+=x1;x1=rot(x1,17);x1^=x0; x0+=x1;x1=rot(x1,29);x1^=x0; x0+=x1;x1=rot(x1,16);x1^=x0; x0+=x1;x1=rot(x1,24);x1^=x0;
    x0+=k2; x1+=k0+2u;
    x0+=x1;x1=rot(x1,13);x1^=x0; x0+=x1;x1=rot(x1,15);x1^=x0; x0+=x1;x1=rot(x1,26);x1^=x0; x0+=x1;x1=rot(x1,6);x1^=x0;
    x0+=k0; x1+=k1+3u;
    x0+=x1;x1=rot(x1,17);x1^=x0; x0+=x1;x1=rot(x1,29);x1^=x0; x0+=x1;x1=rot(x1,16);x1^=x0; x0+=x1;x1=rot(x1,24);x1^=x0;
    x0+=k1; x1+=k2+4u;
    x0+=x1;x1=rot(x1,13);x1^=x0; x0+=x1;x1=rot(x1,15);x1^=x0; x0+=x1;x1=rot(x1,26);x1^=x0; x0+=x1;x1=rot(x1,6);x1^=x0;
    x0+=k2; x1+=k0+5u;
}
// prefill GEMM (verbatim r14)
__device__ void gemmP(const float* __restrict__ A, const float* __restrict__ Bm,
                      float* __restrict__ C, int M, int N, int K,
                      int msplit, long bstride, int dogelu, float* S){
    float* As = S; float* Bs = S + 1024;
    int tid = threadIdx.x, tx = tid&15, ty = tid>>4;
    int tm = M>>6, tn = N>>6;
    for (int t = blockIdx.x; t < tm*tn; t += NB){
        int bm = (t/tn)<<6, bn = (t%tn)<<6;
        float acc[2][4];
        #pragma unroll
        for (int i=0;i<2;i++)
            #pragma unroll
            for (int j=0;j<4;j++) acc[i][j]=0.f;
        for (int k0=0;k0<K;k0+=16){
            #pragma unroll
            for (int ld=0;ld<2;ld++){
                int idx = tid + (ld<<9);
                As[(idx&15)*64 + (idx>>4)]  = A[(size_t)(bm+(idx>>4))*K + k0 + (idx&15)];
                Bs[(idx>>6)*64 + (idx&63)]  = Bm[(size_t)(k0+(idx>>6))*N + bn + (idx&63)];
            }
            __syncthreads();
            #pragma unroll
            for (int k=0;k<16;k++){
                float a0 = As[k*64+ty*2], a1 = As[k*64+ty*2+1];
                float4 bv = *(float4*)&Bs[k*64+tx*4];
                acc[0][0]+=a0*bv.x; acc[0][1]+=a0*bv.y; acc[0][2]+=a0*bv.z; acc[0][3]+=a0*bv.w;
                acc[1][0]+=a1*bv.x; acc[1][1]+=a1*bv.y; acc[1][2]+=a1*bv.z; acc[1][3]+=a1*bv.w;
            }
            __syncthreads();
        }
        #pragma unroll
        for (int i=0;i<2;i++){
            int row = bm + ty*2 + i;
            long rb = (long)(row/msplit)*bstride + (long)(row%msplit)*N;
            #pragma unroll
            for (int j=0;j<4;j++){
                float v = acc[i][j];
                if (dogelu) v = gelu_f(v);
                C[rb + bn + tx*4 + j] = v;
            }
        }
    }
}
__device__ void load_xl(int l,int pos,const float* __restrict__ E,float* S,volatile float* sh){
    int tid = threadIdx.x;
    if (l==0){
        for (int b=0;b<B_;b++){
            int tk = g_tok[b*CW_+pos-1];
            S[b*D_+tid] = E[(size_t)tk*D_+tid];
        }
    } else {
        for (int b=0;b<B_;b++){
            int o = (l-1)*B_*D_ + b*D_;
            S[b*D_+tid] = lnval(g_x1[o+tid]+g_y2[o+tid], sh);
        }
    }
    __syncthreads();
}
__device__ __forceinline__ void wdot4(const float* __restrict__ W, const float* S, float* a){
    int ln = threadIdx.x&31;
    a[0]=a[1]=a[2]=a[3]=0.f;
    #pragma unroll
    for (int kk=0;kk<4;kk++){
        int off = ln*4 + kk*128;
        float4 w = *(const float4*)&W[off];
        #pragma unroll
        for (int b=0;b<4;b++){
            float4 x = *(const float4*)&S[b*D_+off];
            a[b] += w.x*x.x + w.y*x.y + w.z*x.z + w.w*x.w;
        }
    }
    #pragma unroll
    for (int o=16;o;o>>=1){
        #pragma unroll
        for (int b=0;b<4;b++) a[b] += __shfl_down_sync(0xffffffffu,a[b],o);
    }
}
__device__ __forceinline__ float wdot1(const float* __restrict__ W, const float* x){
    int ln = threadIdx.x&31; float a = 0.f;
    #pragma unroll
    for (int kk=0;kk<4;kk++){
        int off = ln*4 + kk*128;
        float4 w = *(const float4*)&W[off];
        float4 xv = *(const float4*)&x[off];
        a += w.x*xv.x + w.y*xv.y + w.z*xv.z + w.w*xv.w;
    }
    #pragma unroll
    for (int o=16;o;o>>=1) a += __shfl_down_sync(0xffffffffu,a,o);
    return a;
}

__global__ void __launch_bounds__(NT,1) mega(
    const int* __restrict__ prompt, const float* __restrict__ E,
    const float* __restrict__ Wq, const float* __restrict__ Wk,
    const float* __restrict__ Wv, const float* __restrict__ Wo,
    const float* __restrict__ W1, const float* __restrict__ W2,
    float* __restrict__ logout, float* __restrict__ tokout){
    extern __shared__ float SV[];
    __shared__ float S[4096];
    __shared__ float sred[16];
    __shared__ float sc[512];
    __shared__ float qsh[DH_];
    __shared__ float stv[TK_];
    __shared__ int sti[TK_];
    __shared__ unsigned long long skey;
    __shared__ int sflag;
    __shared__ int hist[1024];
    __shared__ int wsum[16];
    __shared__ int shB, scand;
    __shared__ float shHi;
    __shared__ unsigned long long candk[256];
    int tid = threadIdx.x, lane = tid&31, wid = tid>>5, bx = blockIdx.x;
    int gw = bx*16 + wid;
    unsigned ep = 0;

    // ---- init (verbatim r14) ----
    for (long i = bx*NT+tid; i < (long)B_*V_; i += (long)NB*NT) g_dis[i] = 0.f;
    for (int i = bx*NT+tid; i < B_*P_; i += NB*NT) g_tok[(i/P_)*CW_ + (i%P_)] = prompt[i];
    for (long i = bx*NT+tid; i < (long)B_*P_*D_; i += (long)NB*NT)
        g_xb[i] = E[(size_t)prompt[i>>9]*D_ + (i&511)];
    for (long i = bx*NT+tid; i < (long)L_*DD; i += (long)NB*NT){
        long l = i/DD, r = i%DD;
        long di = l*DD + (r&511)*D_ + (r>>9);
        g_WqT[di]=Wq[i]; g_WkT[di]=Wk[i]; g_WvT[di]=Wv[i]; g_WoT[di]=Wo[i];
    }
    for (long i = bx*NT+tid; i < (long)L_*DXF; i += (long)NB*NT){
        long l = i/DXF, r = i%DXF;
        g_W1T[l*DXF + (r%DFF_)*D_ + (r/DFF_)] = W1[i];
        g_W2T[l*DXF + (r%D_)*DFF_ + (r/D_)]   = W2[i];
    }
    if (bx < B_){
        if (tid==0) sflag = 0;
        __syncthreads();
        for (int t=tid;t<P_;t+=NT) if (prompt[bx*P_+t]==103) sflag = 1;
        __syncthreads();
        if (tid==0) g_nv[bx] = (prompt[bx*P_+P_-1]==103 || !sflag) ? 1 : 0;
    }
    gsync(ep);

    // ---- prefill (verbatim r14) ----
    for (int l=0;l<L_;l++){
        const float *wq=Wq+(size_t)l*DD, *wk=Wk+(size_t)l*DD, *wv=Wv+(size_t)l*DD;
        const float *wo=Wo+(size_t)l*DD, *w1=W1+(size_t)l*DXF, *w2=W2+(size_t)l*DXF;
        float* kc = g_K  + (size_t)l*B_*CW_*D_;
        float* vc = g_Vv + (size_t)l*B_*CW_*D_;
        gemmP(g_xb, wq, g_q, 512,512,512, 512,0, 0, S);
        gemmP(g_xb, wk, kc,  512,512,512, P_,(long)CW_*D_, 0, S);
        gemmP(g_xb, wv, vc,  512,512,512, P_,(long)CW_*D_, 0, S);
        gsync(ep);
        for (int u=bx; u<B_*8*P_; u+=NB){
            int b = u>>10, h = (u>>7)&7, qi = u&127;
            size_t base = ((size_t)(l*B_+b))*CW_*D_;
            if (tid < DH_) S[tid] = g_q[((size_t)(b*P_+qi))*D_ + h*DH_ + tid];
            __syncthreads();
            int kv = qi+1;
            float s = -3.4e38f;
            if (tid < kv){
                const float* kr = &g_K[base + (size_t)tid*D_ + h*DH_];
                float a = 0.f;
                #pragma unroll
                for (int kk=0;kk<16;kk++){
                    float4 k4 = *(const float4*)&kr[kk*4];
                    a += k4.x*S[kk*4] + k4.y*S[kk*4+1] + k4.z*S[kk*4+2] + k4.w*S[kk*4+3];
                }
                s = a*0.125f;
            }
            float mx = blkMax(s, sred);
            float e = (tid<kv) ? exp_acc(s-mx) : 0.f;
            float sum = blkSum(e, sred);
            sc[tid] = (tid<kv) ? __fdiv_rn(e,sum) : 0.f;
            __syncthreads();
            if (tid < DH_){
                float o = 0.f;
                #pragma unroll 4
                for (int t=0;t<kv;t++) o += sc[t]*g_Vv[base+(size_t)t*D_+h*DH_+tid];
                g_ao[((size_t)(b*P_+qi))*D_ + h*DH_ + tid] = o;
            }
            __syncthreads();
        }
        gsync(ep);
        gemmP(g_ao, wo, g_yb, 512,512,512, 512,0, 0, S);
        gsync(ep);
        for (int r=bx; r<B_*P_; r+=NB)
            g_xb[(size_t)r*D_+tid] = lnval(g_xb[(size_t)r*D_+tid]+g_yb[(size_t)r*D_+tid], sred);
        gsync(ep);
        gemmP(g_xb, w1, g_hp, 512,2048,512, 512,0, 1, S);
        gsync(ep);
        gemmP(g_hp, w2, g_yb, 512,512,2048, 512,0, 0, S);
        gsync(ep);
        for (int r=bx; r<B_*P_; r+=NB)
            g_xb[(size_t)r*D_+tid] = lnval(g_xb[(size_t)r*D_+tid]+g_yb[(size_t)r*D_+tid], sred);
        gsync(ep);
    }

    // ---- decode ----
    for (int s=0;s<STEPS_;s++){
        int pos = P_ + s;
        for (int l=0;l<L_;l++){
            // P1 (verbatim r14)
            if (bx < B_*8){
                int b = bx>>3, h = bx&7;
                load_xl(l, pos, E, S, sred);
                size_t base = ((size_t)(l*B_+b))*CW_*D_;
                for (int j=wid;j<192;j+=16){
                    int ty = j>>6, d = j&63, c = h*DH_+d;
                    const float* W = (ty==0) ? &g_WqT[(size_t)l*DD+(size_t)c*D_]
                                 : (ty==1) ? &g_WkT[(size_t)l*DD+(size_t)c*D_]
                                           : &g_WvT[(size_t)l*DD+(size_t)c*D_];
                    float a = wdot1(W, &S[b*D_]);
                    if (lane==0){
                        if (ty==0) qsh[d] = a;
                        else if (ty==1) g_K [base+(size_t)(pos-1)*D_+c] = a;
                        else            g_Vv[base+(size_t)(pos-1)*D_+c] = a;
                    }
                }
                __syncthreads();
                float sv = -3.4e38f;
                if (tid < pos){
                    const float* kr = &g_K[base+(size_t)tid*D_+h*DH_];
                    float a = 0.f;
                    #pragma unroll
                    for (int kk=0;kk<16;kk++){
                        float4 k4 = *(const float4*)&kr[kk*4];
                        a += k4.x*qsh[kk*4] + k4.y*qsh[kk*4+1] + k4.z*qsh[kk*4+2] + k4.w*qsh[kk*4+3];
                    }
                    sv = a*0.125f;
                }
                float mx = blkMax(sv, sred);
                float e = (tid<pos) ? exp_acc(sv-mx) : 0.f;
                float sum = blkSum(e, sred);
                sc[tid] = (tid<pos) ? __fdiv_rn(e,sum) : 0.f;
                __syncthreads();
                if (tid < DH_){
                    float o = 0.f;
                    #pragma unroll 4
                    for (int t=0;t<pos;t++) o += sc[t]*g_Vv[base+(size_t)t*D_+h*DH_+tid];
                    g_ao[b*D_+h*DH_+tid] = o;
                }
            }
            gsync(ep);
            // P2 (verbatim r14)
            for (int i=tid;i<B_*D_;i+=NT) S[i] = g_ao[i];
            __syncthreads();
            for (int c=gw;c<D_;c+=NWARP){
                float a[4]; wdot4(&g_WoT[(size_t)l*DD+(size_t)c*D_], S, a);
                if (lane==0){
                    #pragma unroll
                    for (int b=0;b<B_;b++) g_y1[b*D_+c] = a[b];
                }
            }
            gsync(ep);
            // P3 (verbatim r14)
            load_xl(l, pos, E, S, sred);
            for (int b=0;b<B_;b++){
                float o0 = lnval(S[b*D_+tid]+g_y1[b*D_+tid], sred);
                S[b*D_+tid]=o0;
                if (bx==0) g_x1[l*B_*D_+b*D_+tid]=o0;
            }
            __syncthreads();
            for (int c=gw;c<DFF_;c+=NWARP){
                float a[4]; wdot4(&g_W1T[(size_t)l*DXF+(size_t)c*D_], S, a);
                if (lane==0){
                    #pragma unroll
                    for (int b=0;b<B_;b++) g_hp[b*DFF_+c] = gelu_f(a[b]);
                }
            }
            gsync(ep);
            // P4 (verbatim r14)
            for (int c=gw;c<D_;c+=NWARP){
                const float* W = &g_W2T[(size_t)l*DXF+(size_t)c*DFF_];
                float a[4] = {0.f,0.f,0.f,0.f};
                #pragma unroll
                for (int kk=0;kk<16;kk++){
                    int off = lane*4 + kk*128;
                    float4 w = *(const float4*)&W[off];
                    #pragma unroll
                    for (int b=0;b<B_;b++){
                        float4 x = *(const float4*)&g_hp[b*DFF_+off];
                        a[b] += w.x*x.x + w.y*x.y + w.z*x.z + w.w*x.w;
                    }
                }
                #pragma unroll
                for (int o=16;o;o>>=1){
                    #pragma unroll
                    for (int b=0;b<B_;b++) a[b] += __shfl_down_sync(0xffffffffu,a[b],o);
                }
                if (lane==0){
                    #pragma unroll
                    for (int b=0;b<B_;b++) g_y2[l*B_*D_+b*D_+c] = a[b];
                }
            }
            gsync(ep);
        }
        // logits + masking (verbatim r14)
        for (int b=0;b<B_;b++){
            int o = 3*B_*D_ + b*D_;
            S[b*D_+tid] = lnval(g_x1[o+tid]+g_y2[o+tid], sred);
        }
        __syncthreads();
        for (int v=gw;v<V_;v+=NWARP){
            float a[4]; wdot4(&E[(size_t)v*D_], S, a);
            if (lane==0){
                #pragma unroll
                for (int b=0;b<B_;b++){
                    float dis;
                    if (g_nv[b]){ dis=0.f; g_dis[(size_t)b*V_+v]=0.f; }
                    else dis = g_dis[(size_t)b*V_+v];
                    float mv = a[b] + dis*(-1e9f);
                    g_mask[(size_t)b*V_+v] = mv;
                    if (logout) logout[(size_t)s*B_*V_+(size_t)b*V_+v] = mv;
                }
            }
        }
        gsync(ep);
        // ---- top-50: value-range bucket select (exact superset + exact rank) ----
        if (bx < B_){
            int b = bx;
            const float* mb = &g_mask[(size_t)b*V_];
            float lv = -3.4e38f;
            for (int k=0;k<40;k++){
                int v = tid + (k<<9);
                if (v < V_){ float x = mb[v]; SV[v] = x; lv = fmaxf(lv, x); }
            }
            float hi = blkMax(lv, sred);
            if (tid==0){ shHi = hi; scand = 0; }
            for (int i=tid;i<1024;i+=NT) hist[i]=0;
            __syncthreads();
            float lo = shHi - 8.0f;
            for (int k=0;k<40;k++){
                int v = tid + (k<<9);
                if (v < V_){
                    int bi = (int)fminf(fmaxf((SV[v]-lo)*128.0f, 0.0f), 1023.0f);
                    atomicAdd(&hist[bi], 1);
                }
            }
            __syncthreads();
            {   int sacc = hist[tid*2] + hist[tid*2+1];
                #pragma unroll
                for (int o=16;o;o>>=1) sacc += __shfl_down_sync(0xffffffffu,sacc,o);
                if (lane==0) wsum[wid] = sacc;
            }
            __syncthreads();
            if (tid==0){
                int cum=0, g=15;
                for (; g>0; g--){ if (cum + wsum[g] >= TK_) break; cum += wsum[g]; }
                int bkt = g*64+63;
                for (; bkt>g*64; bkt--){ int c=hist[bkt]; if (cum+c>=TK_) break; cum+=c; }
                shB = bkt;
            }
            __syncthreads();
            int Bsel = shB;
            for (int k=0;k<40;k++){
                int v = tid + (k<<9);
                if (v < V_){
                    int bi = (int)fminf(fmaxf((SV[v]-lo)*128.0f, 0.0f), 1023.0f);
                    if (bi >= Bsel){
                        int slot = atomicAdd(&scand, 1);
                        if (slot < 256)
                            candk[slot] = ((unsigned long long)ordf(SV[v])<<32) | (unsigned)(0xFFFFFFFFu-(unsigned)v);
                    }
                }
            }
            __syncthreads();
            int nc = scand;
            if (nc >= TK_ && nc <= 256){
                if (tid < nc){
                    unsigned long long mykey = candk[tid];
                    int rank = 0;
                    for (int j=0;j<nc;j++) if (candk[j] > mykey) rank++;
                    if (rank < TK_){
                        sti[rank] = (int)(0xFFFFFFFFu-(unsigned)(mykey&0xFFFFFFFFull));
                        stv[rank] = dordf((unsigned)(mykey>>32));
                    }
                }
                __syncthreads();
            } else {
                // fallback: serial extraction (verbatim r14)
                uint64_t tk0 = 0ull;
                float lv2=-3.4e38f; int li=0x7fffffff;
                for (int k=0;k<40;k++){
                    int v = tid + (k<<9);
                    if (v < V_){ float x = SV[v]; if (x > lv2){ lv2=x; li=v; } }
                }
                for (int r=0;r<TK_;r++){
                    if (tid==0) skey = 0ull;
                    __syncthreads();
                    unsigned long long key = ((unsigned long long)ordf(lv2)<<32) | (unsigned)(0xFFFFFFFFu-(unsigned)li);
                    #pragma unroll
                    for (int o=16;o;o>>=1){
                        unsigned long long t2 = __shfl_down_sync(0xffffffffu,key,o);
                        if (t2 > key) key = t2;
                    }
                    if (lane==0) atomicMax(&skey, key);
                    __syncthreads();
                    unsigned long long win = skey;
                    int gi = (int)(0xFFFFFFFFu-(unsigned)(win&0xFFFFFFFFull));
                    if (tid==0){ sti[r]=gi; stv[r]=dordf((unsigned)(win>>32)); }
                    if ((gi&511) == tid){
                        tk0 |= 1ull << (gi>>9);
                        lv2=-3.4e38f; li=0x7fffffff;
                        for (int k=0;k<40;k++){
                            if ((tk0>>k)&1ull) continue;
                            int v = tid + (k<<9);
                            if (v < V_){ float x = SV[v]; if (x > lv2){ lv2=x; li=v; } }
                        }
                    }
                    __syncthreads();
                }
            }
            // Gumbel-max (verbatim r14)
            if (tid==0) skey = 0ull;
            __syncthreads();
            if (tid < TK_){
                int j = b*TK_ + tid;
                uint32_t c0=0u, c1=(uint32_t)s;
                tf2x32(0u,42u,c0,c1);
                uint32_t x0=0u, x1=(uint32_t)j;
                tf2x32(c0,c1,x0,x1);
                uint32_t bits = x0 ^ x1;
                float u = __uint_as_float((bits>>9)|0x3f800000u) - 1.0f;
                const float tinyf = 1.17549435e-38f;
                u = fmaxf(tinyf, u + tinyf);
                float g = (float)(-log(-log((double)u)));
                float cand = stv[tid] + g;
                unsigned long long key = ((unsigned long long)ordf(cand)<<32) | (unsigned)(0xFFFFFFFFu-(unsigned)tid);
                atomicMax(&skey, key);
            }
            __syncthreads();
            if (tid==0){
                int r = (int)(0xFFFFFFFFu-(unsigned)(skey&0xFFFFFFFFull));
                int stok = sti[r];
                g_dis[(size_t)b*V_+stok] += 1.0f;
                int last = g_tok[b*CW_+pos-1];
                g_tok[b*CW_+pos] = (last>=3 && last<=102) ? 103 : stok;
                sflag = 0;
            }
            __syncthreads();
            for (int t=tid;t<=pos;t+=NT) if (g_tok[b*CW_+t]==103) sflag = 1;
            __syncthreads();
            if (tid==0) g_nv[b] = (g_tok[b*CW_+pos]==103 || !sflag) ? 1 : 0;
        }
        gsync(ep);
    }
    if (tokout)
        for (int i=bx*NT+tid;i<B_*CW_;i+=NB*NT) tokout[i] = (float)g_tok[i];
}

extern "C" void kernel_launch(void* const* d_in, const int* in_sizes, int n_in,
                              void* d_out, int out_size){
    const int*   prompt = (const int*)d_in[0];
    const float* E  = (const float*)d_in[1];
    const float* Wq = (const float*)d_in[2];
    const float* Wk = (const float*)d_in[3];
    const float* Wv = (const float*)d_in[4];
    const float* Wo = (const float*)d_in[5];
    const float* W1 = (const float*)d_in[6];
    const float* W2 = (const float*)d_in[7];
    float* out = (float*)d_out;
    const long NL = (long)STEPS_*B_*V_;
    float* tok_out = 0; float* log_out = 0;
    if ((long)out_size >= 768L + NL){ tok_out = out; log_out = out + 768; }
    else if ((long)out_size >= NL)  { log_out = out; }
    else                            { tok_out = out; }
    unsigned zero = 0;
    cudaMemcpyToSymbolAsync(g_arr, &zero, 4, 0, cudaMemcpyHostToDevice);
    cudaMemcpyToSymbolAsync(g_rel, &zero, 4, 0, cudaMemcpyHostToDevice);
    static int smem_set = 0;
    if (!smem_set){
        cudaFuncSetAttribute(mega, cudaFuncAttributeMaxDynamicSharedMemorySize, V_*4);
        smem_set = 1;
    }
    mega<<<NB, NT, V_*4>>>(prompt, E, Wq, Wk, Wv, Wo, W1, W2, log_out, tok_out);
}

// round 17
// speedup vs baseline: 1.2509x; 1.2509x over previous
#include <cuda_runtime.h>
#include <math.h>
#include <stdint.h>
#define B_ 4
#define V_ 20000
#define D_ 512
#define DH_ 64
#define L_ 4
#define DFF_ 2048
#define P_ 128
#define CW_ 192
#define STEPS_ 64
#define TK_ 50
#define NB 148
#define NT 512
#define NWARP (NB*16)
#define DD (D_*D_)
#define DXF (D_*DFF_)

__device__ float g_K[L_*B_*CW_*D_], g_Vv[L_*B_*CW_*D_];
__device__ float g_WqT[L_*DD], g_WkT[L_*DD], g_WvT[L_*DD], g_WoT[L_*DD];
__device__ float g_W1T[L_*DXF], g_W2T[L_*DXF];
__device__ float g_q[B_*P_*D_], g_xb[B_*P_*D_], g_yb[B_*P_*D_], g_ao[B_*P_*D_];
__device__ float g_hp[B_*P_*DFF_];
__device__ float g_y1[B_*D_], g_x1[L_*B_*D_], g_y2[L_*B_*D_];
__device__ float g_xl[B_*D_];
__device__ float g_mask[B_*V_], g_dis[B_*V_];
__device__ int g_tok[B_*CW_], g_nv[B_];
__device__ unsigned g_cnt = 0;
__device__ volatile unsigned g_sense = 0;

__device__ __forceinline__ void gsync(){
    __syncthreads();
    if (threadIdx.x == 0){
        __threadfence();
        unsigned s = g_sense;
        if (atomicAdd(&g_cnt,1u) == NB-1u){ atomicExch(&g_cnt,0u); __threadfence(); g_sense = s+1u; }
        else while (g_sense == s) {}
        __threadfence();
    }
    __syncthreads();
}
__device__ __forceinline__ float gelu_f(float x){
    double xd = x;
    return (float)(0.5*xd*(1.0 + tanh(0.7978845608028654*(xd + 0.044715*xd*xd*xd))));
}
__device__ __forceinline__ float exp_acc(float x){ return (float)exp((double)x); }
__device__ __forceinline__ float blkSum(float v, volatile float* sh){
    int ln = threadIdx.x&31, w = threadIdx.x>>5;
    #pragma unroll
    for (int o=16;o;o>>=1) v += __shfl_down_sync(0xffffffffu,v,o);
    if (ln==0) sh[w]=v;
    __syncthreads();
    if (threadIdx.x==0){ float r=sh[0]; for(int i=1;i<16;i++) r+=sh[i]; sh[0]=r; }
    __syncthreads(); float r=sh[0]; __syncthreads(); return r;
}
__device__ __forceinline__ float blkMax(float v, volatile float* sh){
    int ln = threadIdx.x&31, w = threadIdx.x>>5;
    #pragma unroll
    for (int o=16;o;o>>=1) v = fmaxf(v,__shfl_down_sync(0xffffffffu,v,o));
    if (ln==0) sh[w]=v;
    __syncthreads();
    if (threadIdx.x==0){ float r=sh[0]; for(int i=1;i<16;i++) r=fmaxf(r,sh[i]); sh[0]=r; }
    __syncthreads(); float r=sh[0]; __syncthreads(); return r;
}
__device__ __forceinline__ float lnval(float v, volatile float* sh){
    float m = blkSum(v,sh)*(1.0f/D_);
    float d = v-m;
    float var = blkSum(d*d,sh)*(1.0f/D_);
    return d*(float)(1.0/sqrt((double)var+1e-6));
}
__device__ __forceinline__ unsigned ordf(float x){
    unsigned u=__float_as_uint(x);
    return u ^ (((unsigned)((int)u>>31)) | 0x80000000u);
}
__device__ __forceinline__ float dordf(unsigned e){
    unsigned u = (e&0x80000000u) ? (e^0x80000000u) : ~e;
    return __uint_as_float(u);
}
__device__ __forceinline__ uint32_t rot(uint32_t x,int r){ return (x<<r)|(x>>(32-r)); }
__device__ __forceinline__ void tf2x32(uint32_t k0,uint32_t k1,uint32_t&x0,uint32_t&x1){
    uint32_t k2 = k0^k1^0x1BD11BDAu;
    x0+=k0; x1+=k1;
    x0+=x1;x1=rot(x1,13);x1^=x0; x0+=x1;x1=rot(x1,15);x1^=x0; x0+=x1;x1=rot(x1,26);x1^=x0; x0+=x1;x1=rot(x1,6);x1^=x0;
    x0+=k1; x1+=k2+1u;
    x0+=x1;x1=rot(x1,17);x1^=x0; x0+=x1;x1=rot(x1,29);x1^=x0; x0+=x1;x1=rot(x1,16);x1^=x0; x0+=x1;x1=rot(x1,24);x1^=x0;
    x0+=k2; x1+=k0+2u;
    x0+=x1;x1=rot(x1,13);x1^=x0; x0+=x1;x1=rot(x1,15);x1^=x0; x0+=x1;x1=rot(x1,26);x1^=x0; x0+=x1;x1=rot(x1,6);x1^=x0;
    x0+=k0; x1+=k1+3u;
    x0+=x1;x1=rot(x1,17);x1^=x0; x0+=x1;x1=rot(x1,29);x1^=x0; x0+=x1;x1=rot(x1,16);x1^=x0; x0+=x1;x1=rot(x1,24);x1^=x0;
    x0+=k1; x1+=k2+4u;
    x0+=x1;x1=rot(x1,13);x1^=x0; x0+=x1;x1=rot(x1,15);x1^=x0; x0+=x1;x1=rot(x1,26);x1^=x0; x0+=x1;x1=rot(x1,6);x1^=x0;
    x0+=k2; x1+=k0+5u;
}
// prefill GEMM, 64x64 tile (verbatim r14)
__device__ void gemmP(const float* __restrict__ A, const float* __restrict__ Bm,
                      float* __restrict__ C, int M, int N, int K,
                      int msplit, long bstride, int dogelu, float* S){
    float* As = S; float* Bs = S + 1024;
    int tid = threadIdx.x, tx = tid&15, ty = tid>>4;
    int tm = M>>6, tn = N>>6;
    for (int t = blockIdx.x; t < tm*tn; t += NB){
        int bm = (t/tn)<<6, bn = (t%tn)<<6;
        float acc[2][4];
        #pragma unroll
        for (int i=0;i<2;i++)
            #pragma unroll
            for (int j=0;j<4;j++) acc[i][j]=0.f;
        for (int k0=0;k0<K;k0+=16){
            #pragma unroll
            for (int ld=0;ld<2;ld++){
                int idx = tid + (ld<<9);
                As[(idx&15)*64 + (idx>>4)]  = A[(size_t)(bm+(idx>>4))*K + k0 + (idx&15)];
                Bs[(idx>>6)*64 + (idx&63)]  = Bm[(size_t)(k0+(idx>>6))*N + bn + (idx&63)];
            }
            __syncthreads();
            #pragma unroll
            for (int k=0;k<16;k++){
                float a0 = As[k*64+ty*2], a1 = As[k*64+ty*2+1];
                float4 bv = *(float4*)&Bs[k*64+tx*4];
                acc[0][0]+=a0*bv.x; acc[0][1]+=a0*bv.y; acc[0][2]+=a0*bv.z; acc[0][3]+=a0*bv.w;
                acc[1][0]+=a1*bv.x; acc[1][1]+=a1*bv.y; acc[1][2]+=a1*bv.z; acc[1][3]+=a1*bv.w;
            }
            __syncthreads();
        }
        #pragma unroll
        for (int i=0;i<2;i++){
            int row = bm + ty*2 + i;
            long rb = (long)(row/msplit)*bstride + (long)(row%msplit)*N;
            #pragma unroll
            for (int j=0;j<4;j++){
                float v = acc[i][j];
                if (dogelu) v = gelu_f(v);
                C[rb + bn + tx*4 + j] = v;
            }
        }
    }
}
__device__ void load_xl(int l,int pos,const float* __restrict__ E,float* S,volatile float* sh){
    int tid = threadIdx.x;
    if (l==0){
        for (int b=0;b<B_;b++){
            int tk = g_tok[b*CW_+pos-1];
            S[b*D_+tid] = E[(size_t)tk*D_+tid];
        }
    } else {
        for (int b=0;b<B_;b++){
            int o = (l-1)*B_*D_ + b*D_;
            S[b*D_+tid] = lnval(g_x1[o+tid]+g_y2[o+tid], sh);
        }
    }
    __syncthreads();
}
__device__ __forceinline__ void wdot4(const float* __restrict__ W, const float* S, float* a){
    int ln = threadIdx.x&31;
    a[0]=a[1]=a[2]=a[3]=0.f;
    #pragma unroll
    for (int kk=0;kk<4;kk++){
        int off = ln*4 + kk*128;
        float4 w = *(const float4*)&W[off];
        #pragma unroll
        for (int b=0;b<4;b++){
            float4 x = *(const float4*)&S[b*D_+off];
            a[b] += w.x*x.x + w.y*x.y + w.z*x.z + w.w*x.w;
        }
    }
    #pragma unroll
    for (int o=16;o;o>>=1){
        #pragma unroll
        for (int b=0;b<4;b++) a[b] += __shfl_down_sync(0xffffffffu,a[b],o);
    }
}
// paired wdot4: two weight rows, interleaved loads, per-row math identical to wdot4
__device__ __forceinline__ void wdot4p(const float* __restrict__ Wa, const float* __restrict__ Wb,
                                       const float* S, float* a, float* c){
    int ln = threadIdx.x&31;
    #pragma unroll
    for (int kk=0;kk<4;kk++){
        int off = ln*4 + kk*128;
        float4 wa = *(const float4*)&Wa[off];
        float4 wb = *(const float4*)&Wb[off];
        #pragma unroll
        for (int b=0;b<4;b++){
            float4 x = *(const float4*)&S[b*D_+off];
            a[b] += wa.x*x.x + wa.y*x.y + wa.z*x.z + wa.w*x.w;
            c[b] += wb.x*x.x + wb.y*x.y + wb.z*x.z + wb.w*x.w;
        }
    }
    #pragma unroll
    for (int o=16;o;o>>=1){
        #pragma unroll
        for (int b=0;b<4;b++){
            a[b] += __shfl_down_sync(0xffffffffu,a[b],o);
            c[b] += __shfl_down_sync(0xffffffffu,c[b],o);
        }
    }
}
// paired single-row dots (two independent chains, each identical to wdot1)
__device__ __forceinline__ void wdot2(const float* __restrict__ Wa, const float* __restrict__ Wb,
                                      const float* x, float &a, float &c){
    int ln = threadIdx.x&31; a = 0.f; c = 0.f;
    #pragma unroll
    for (int kk=0;kk<4;kk++){
        int off = ln*4 + kk*128;
        float4 wa = *(const float4*)&Wa[off];
        float4 wb = *(const float4*)&Wb[off];
        float4 xv = *(const float4*)&x[off];
        a += wa.x*xv.x + wa.y*xv.y + wa.z*xv.z + wa.w*xv.w;
        c += wb.x*xv.x + wb.y*xv.y + wb.z*xv.z + wb.w*xv.w;
    }
    #pragma unroll
    for (int o=16;o;o>>=1){
        a += __shfl_down_sync(0xffffffffu,a,o);
        c += __shfl_down_sync(0xffffffffu,c,o);
    }
}

__global__ void __launch_bounds__(NT,1) mega(
    const int* __restrict__ prompt, const float* __restrict__ E,
    const float* __restrict__ Wq, const float* __restrict__ Wk,
    const float* __restrict__ Wv, const float* __restrict__ Wo,
    const float* __restrict__ W1, const float* __restrict__ W2,
    float* __restrict__ logout, float* __restrict__ tokout){
    extern __shared__ float SV[];
    __shared__ float S[4096];
    __shared__ float sred[16];
    __shared__ float sc[512];
    __shared__ float qsh[DH_];
    __shared__ float stv[TK_];
    __shared__ int sti[TK_];
    __shared__ unsigned long long skey;
    __shared__ int sflag;
    int tid = threadIdx.x, lane = tid&31, wid = tid>>5, bx = blockIdx.x;
    int gw = bx*16 + wid;

    // ---- init (verbatim r14) ----
    for (long i = bx*NT+tid; i < (long)B_*V_; i += (long)NB*NT) g_dis[i] = 0.f;
    for (int i = bx*NT+tid; i < B_*P_; i += NB*NT) g_tok[(i/P_)*CW_ + (i%P_)] = prompt[i];
    for (long i = bx*NT+tid; i < (long)B_*P_*D_; i += (long)NB*NT)
        g_xb[i] = E[(size_t)prompt[i>>9]*D_ + (i&511)];
    for (long i = bx*NT+tid; i < (long)L_*DD; i += (long)NB*NT){
        long l = i/DD, r = i%DD;
        long di = l*DD + (r&511)*D_ + (r>>9);
        g_WqT[di]=Wq[i]; g_WkT[di]=Wk[i]; g_WvT[di]=Wv[i]; g_WoT[di]=Wo[i];
    }
    for (long i = bx*NT+tid; i < (long)L_*DXF; i += (long)NB*NT){
        long l = i/DXF, r = i%DXF;
        g_W1T[l*DXF + (r%DFF_)*D_ + (r/DFF_)] = W1[i];
        g_W2T[l*DXF + (r%D_)*DFF_ + (r/D_)]   = W2[i];
    }
    if (bx < B_){
        if (tid==0) sflag = 0;
        __syncthreads();
        for (int t=tid;t<P_;t+=NT) if (prompt[bx*P_+t]==103) sflag = 1;
        __syncthreads();
        if (tid==0) g_nv[bx] = (prompt[bx*P_+P_-1]==103 || !sflag) ? 1 : 0;
    }
    gsync();

    // ---- prefill (verbatim r14 + unroll on V-accum) ----
    for (int l=0;l<L_;l++){
        const float *wq=Wq+(size_t)l*DD, *wk=Wk+(size_t)l*DD, *wv=Wv+(size_t)l*DD;
        const float *wo=Wo+(size_t)l*DD, *w1=W1+(size_t)l*DXF, *w2=W2+(size_t)l*DXF;
        float* kc = g_K  + (size_t)l*B_*CW_*D_;
        float* vc = g_Vv + (size_t)l*B_*CW_*D_;
        gemmP(g_xb, wq, g_q, 512,512,512, 512,0, 0, S);
        gemmP(g_xb, wk, kc,  512,512,512, P_,(long)CW_*D_, 0, S);
        gemmP(g_xb, wv, vc,  512,512,512, P_,(long)CW_*D_, 0, S);
        gsync();
        for (int u=bx; u<B_*8*P_; u+=NB){
            int b = u>>10, h = (u>>7)&7, qi = u&127;
            size_t base = ((size_t)(l*B_+b))*CW_*D_;
            if (tid < DH_) S[tid] = g_q[((size_t)(b*P_+qi))*D_ + h*DH_ + tid];
            __syncthreads();
            int kv = qi+1;
            float s = -3.4e38f;
            if (tid < kv){
                const float* kr = &g_K[base + (size_t)tid*D_ + h*DH_];
                float a = 0.f;
                #pragma unroll
                for (int kk=0;kk<16;kk++){
                    float4 k4 = *(const float4*)&kr[kk*4];
                    a += k4.x*S[kk*4] + k4.y*S[kk*4+1] + k4.z*S[kk*4+2] + k4.w*S[kk*4+3];
                }
                s = a*0.125f;
            }
            float mx = blkMax(s, sred);
            float e = (tid<kv) ? exp_acc(s-mx) : 0.f;
            float sum = blkSum(e, sred);
            sc[tid] = (tid<kv) ? __fdiv_rn(e,sum) : 0.f;
            __syncthreads();
            if (tid < DH_){
                float o = 0.f;
                #pragma unroll 16
                for (int t=0;t<kv;t++) o += sc[t]*g_Vv[base+(size_t)t*D_+h*DH_+tid];
                g_ao[((size_t)(b*P_+qi))*D_ + h*DH_ + tid] = o;
            }
            __syncthreads();
        }
        gsync();
        gemmP(g_ao, wo, g_yb, 512,512,512, 512,0, 0, S);
        gsync();
        for (int r=bx; r<B_*P_; r+=NB)
            g_xb[(size_t)r*D_+tid] = lnval(g_xb[(size_t)r*D_+tid]+g_yb[(size_t)r*D_+tid], sred);
        gsync();
        gemmP(g_xb, w1, g_hp, 512,2048,512, 512,0, 1, S);
        gsync();
        gemmP(g_hp, w2, g_yb, 512,512,2048, 512,0, 0, S);
        gsync();
        for (int r=bx; r<B_*P_; r+=NB)
            g_xb[(size_t)r*D_+tid] = lnval(g_xb[(size_t)r*D_+tid]+g_yb[(size_t)r*D_+tid], sred);
        gsync();
    }

    // ---- decode ----
    for (int s=0;s<STEPS_;s++){
        int pos = P_ + s;
        for (int l=0;l<L_;l++){
            // P1: fused QKV(paired) + attention; block 0 caches x -> g_xl
            if (bx < B_*8){
                int b = bx>>3, h = bx&7;
                load_xl(l, pos, E, S, sred);
                if (bx==0)
                    for (int i=tid;i<B_*D_;i+=NT) g_xl[i] = S[i];
                size_t base = ((size_t)(l*B_+b))*CW_*D_;
                for (int p=0;p<6;p++){
                    int jA = wid + 32*p;
                    int ty = jA>>6, dA = jA&63, dB = dA+16;
                    const float* Wm = (ty==0) ? &g_WqT[(size_t)l*DD]
                                 : (ty==1) ? &g_WkT[(size_t)l*DD]
                                           : &g_WvT[(size_t)l*DD];
                    int cA = h*DH_+dA, cB = h*DH_+dB;
                    float aA, aB;
                    wdot2(&Wm[(size_t)cA*D_], &Wm[(size_t)cB*D_], &S[b*D_], aA, aB);
                    if (lane==0){
                        if (ty==0){ qsh[dA]=aA; qsh[dB]=aB; }
                        else if (ty==1){ g_K [base+(size_t)(pos-1)*D_+cA]=aA; g_K [base+(size_t)(pos-1)*D_+cB]=aB; }
                        else           { g_Vv[base+(size_t)(pos-1)*D_+cA]=aA; g_Vv[base+(size_t)(pos-1)*D_+cB]=aB; }
                    }
                }
                __syncthreads();
                float sv = -3.4e38f;
                if (tid < pos){
                    const float* kr = &g_K[base+(size_t)tid*D_+h*DH_];
                    float a = 0.f;
                    #pragma unroll
                    for (int kk=0;kk<16;kk++){
                        float4 k4 = *(const float4*)&kr[kk*4];
                        a += k4.x*qsh[kk*4] + k4.y*qsh[kk*4+1] + k4.z*qsh[kk*4+2] + k4.w*qsh[kk*4+3];
                    }
                    sv = a*0.125f;
                }
                float mx = blkMax(sv, sred);
                float e = (tid<pos) ? exp_acc(sv-mx) : 0.f;
                float sum = blkSum(e, sred);
                sc[tid] = (tid<pos) ? __fdiv_rn(e,sum) : 0.f;
                __syncthreads();
                if (tid < DH_){
                    float o = 0.f;
                    #pragma unroll 16
                    for (int t=0;t<pos;t++) o += sc[t]*g_Vv[base+(size_t)t*D_+h*DH_+tid];
                    g_ao[b*D_+h*DH_+tid] = o;
                }
            }
            gsync();
            // P2: O-projection (verbatim r14)
            for (int i=tid;i<B_*D_;i+=NT) S[i] = g_ao[i];
            __syncthreads();
            for (int c=gw;c<D_;c+=NWARP){
                float a[4]; wdot4(&g_WoT[(size_t)l*DD+(size_t)c*D_], S, a);
                if (lane==0){
                    #pragma unroll
                    for (int b=0;b<B_;b++) g_y1[b*D_+c] = a[b];
                }
            }
            gsync();
            // P3: x from g_xl (cached LN), then x1 = LN(x + y1); FFN1 + gelu
            for (int b=0;b<B_;b++) S[b*D_+tid] = g_xl[b*D_+tid];
            __syncthreads();
            for (int b=0;b<B_;b++){
                float o0 = lnval(S[b*D_+tid]+g_y1[b*D_+tid], sred);
                S[b*D_+tid]=o0;
                if (bx==0) g_x1[l*B_*D_+b*D_+tid]=o0;
            }
            __syncthreads();
            for (int c=gw;c<DFF_;c+=NWARP){
                float a[4]; wdot4(&g_W1T[(size_t)l*DXF+(size_t)c*D_], S, a);
                if (lane==0){
                    #pragma unroll
                    for (int b=0;b<B_;b++) g_hp[b*DFF_+c] = gelu_f(a[b]);
                }
            }
            gsync();
            // P4: FFN2 (verbatim r14)
            for (int c=gw;c<D_;c+=NWARP){
                const float* W = &g_W2T[(size_t)l*DXF+(size_t)c*DFF_];
                float a[4] = {0.f,0.f,0.f,0.f};
                #pragma unroll
                for (int kk=0;kk<16;kk++){
                    int off = lane*4 + kk*128;
                    float4 w = *(const float4*)&W[off];
                    #pragma unroll
                    for (int b=0;b<B_;b++){
                        float4 x = *(const float4*)&g_hp[b*DFF_+off];
                        a[b] += w.x*x.x + w.y*x.y + w.z*x.z + w.w*x.w;
                    }
                }
                #pragma unroll
                for (int o=16;o;o>>=1){
                    #pragma unroll
                    for (int b=0;b<B_;b++) a[b] += __shfl_down_sync(0xffffffffu,a[b],o);
                }
                if (lane==0){
                    #pragma unroll
                    for (int b=0;b<B_;b++) g_y2[l*B_*D_+b*D_+c] = a[b];
                }
            }
            gsync();
        }
        // logits + masking (paired rows)
        for (int b=0;b<B_;b++){
            int o = 3*B_*D_ + b*D_;
            S[b*D_+tid] = lnval(g_x1[o+tid]+g_y2[o+tid], sred);
        }
        __syncthreads();
        {
            int v = gw;
            for (; v + NWARP < V_; v += 2*NWARP){
                int v2 = v + NWARP;
                float a[4]={0.f,0.f,0.f,0.f}, c2[4]={0.f,0.f,0.f,0.f};
                wdot4p(&E[(size_t)v*D_], &E[(size_t)v2*D_], S, a, c2);
                if (lane==0){
                    #pragma unroll
                    for (int b=0;b<B_;b++){
                        float dis;
                        if (g_nv[b]){ dis=0.f; g_dis[(size_t)b*V_+v]=0.f; }
                        else dis = g_dis[(size_t)b*V_+v];
                        float mv = a[b] + dis*(-1e9f);
                        g_mask[(size_t)b*V_+v] = mv;
                        if (logout) logout[(size_t)s*B_*V_+(size_t)b*V_+v] = mv;
                        float dis2;
                        if (g_nv[b]){ dis2=0.f; g_dis[(size_t)b*V_+v2]=0.f; }
                        else dis2 = g_dis[(size_t)b*V_+v2];
                        float mv2 = c2[b] + dis2*(-1e9f);
                        g_mask[(size_t)b*V_+v2] = mv2;
                        if (logout) logout[(size_t)s*B_*V_+(size_t)b*V_+v2] = mv2;
                    }
                }
            }
            for (; v < V_; v += NWARP){
                float a[4]; wdot4(&E[(size_t)v*D_], S, a);
                if (lane==0){
                    #pragma unroll
                    for (int b=0;b<B_;b++){
                        float dis;
                        if (g_nv[b]){ dis=0.f; g_dis[(size_t)b*V_+v]=0.f; }
                        else dis = g_dis[(size_t)b*V_+v];
                        float mv = a[b] + dis*(-1e9f);
                        g_mask[(size_t)b*V_+v] = mv;
                        if (logout) logout[(size_t)s*B_*V_+(size_t)b*V_+v] = mv;
                    }
                }
            }
        }
        gsync();
        // top-50 + Threefry Gumbel-max (verbatim r14 serial sampler)
        if (bx < B_){
            int b = bx;
            const float* mb = &g_mask[(size_t)b*V_];
            uint64_t tk0 = 0ull;
            float lv=-3.4e38f; int li=0x7fffffff;
            for (int k=0;k<40;k++){
                int v = tid + (k<<9);
                if (v < V_){ float x = mb[v]; SV[v] = x; if (x > lv){ lv=x; li=v; } }
            }
            for (int r=0;r<TK_;r++){
                if (tid==0) skey = 0ull;
                __syncthreads();
                unsigned long long key = ((unsigned long long)ordf(lv)<<32) | (unsigned)(0xFFFFFFFFu-(unsigned)li);
                #pragma unroll
                for (int o=16;o;o>>=1){
                    unsigned long long t2 = __shfl_down_sync(0xffffffffu,key,o);
                    if (t2 > key) key = t2;
                }
                if (lane==0) atomicMax(&skey, key);
                __syncthreads();
                unsigned long long win = skey;
                int gi = (int)(0xFFFFFFFFu-(unsigned)(win&0xFFFFFFFFull));
                if (tid==0){ sti[r]=gi; stv[r]=dordf((unsigned)(win>>32)); }
                if ((gi&511) == tid){
                    tk0 |= 1ull << (gi>>9);
                    lv=-3.4e38f; li=0x7fffffff;
                    for (int k=0;k<40;k++){
                        if ((tk0>>k)&1ull) continue;
                        int v = tid + (k<<9);
                        if (v < V_){ float x = SV[v]; if (x > lv){ lv=x; li=v; } }
                    }
                }
                __syncthreads();
            }
            if (tid==0) skey = 0ull;
            __syncthreads();
            if (tid < TK_){
                int j = b*TK_ + tid;
                uint32_t c0=0u, c1=(uint32_t)s;
                tf2x32(0u,42u,c0,c1);
                uint32_t x0=0u, x1=(uint32_t)j;
                tf2x32(c0,c1,x0,x1);
                uint32_t bits = x0 ^ x1;
                float u = __uint_as_float((bits>>9)|0x3f800000u) - 1.0f;
                const float tinyf = 1.17549435e-38f;
                u = fmaxf(tinyf, u + tinyf);
                float g = (float)(-log(-log((double)u)));
                float cand = stv[tid] + g;
                unsigned long long key = ((unsigned long long)ordf(cand)<<32) | (unsigned)(0xFFFFFFFFu-(unsigned)tid);
                atomicMax(&skey, key);
            }
            __syncthreads();
            if (tid==0){
                int r = (int)(0xFFFFFFFFu-(unsigned)(skey&0xFFFFFFFFull));
                int stok = sti[r];
                g_dis[(size_t)b*V_+stok] += 1.0f;
                int last = g_tok[b*CW_+pos-1];
                g_tok[b*CW_+pos] = (last>=3 && last<=102) ? 103 : stok;
                sflag = 0;
            }
            __syncthreads();
            for (int t=tid;t<=pos;t+=NT) if (g_tok[b*CW_+t]==103) sflag = 1;
            __syncthreads();
            if (tid==0) g_nv[b] = (g_tok[b*CW_+pos]==103 || !sflag) ? 1 : 0;
        }
        gsync();
    }
    if (tokout)
        for (int i=bx*NT+tid;i<B_*CW_;i+=NB*NT) tokout[i] = (float)g_tok[i];
}

extern "C" void kernel_launch(void* const* d_in, const int* in_sizes, int n_in,
                              void* d_out, int out_size){
    const int*   prompt = (const int*)d_in[0];
    const float* E  = (const float*)d_in[1];
    const float* Wq = (const float*)d_in[2];
    const float* Wk = (const float*)d_in[3];
    const float* Wv = (const float*)d_in[4];
    const float* Wo = (const float*)d_in[5];
    const float* W1 = (const float*)d_in[6];
    const float* W2 = (const float*)d_in[7];
    float* out = (float*)d_out;
    const long NL = (long)STEPS_*B_*V_;
    float* tok_out = 0; float* log_out = 0;
    if ((long)out_size >= 768L + NL){ tok_out = out; log_out = out + 768; }
    else if ((long)out_size >= NL)  { log_out = out; }
    else                            { tok_out = out; }
    static int smem_set = 0;
    if (!smem_set){
        cudaFuncSetAttribute(mega, cudaFuncAttributeMaxDynamicSharedMemorySize, V_*4);
        smem_set = 1;
    }
    mega<<<NB, NT, V_*4>>>(prompt, E, Wq, Wk, Wv, Wo, W1, W2, log_out, tok_out);
}